// round 1
// baseline (speedup 1.0000x reference)
#include <cuda_runtime.h>
#include <math.h>

// Recognition_RNN: h_new = tanh([x,h] @ W_i2h^T + b_i2h); out = h_new @ W_h2o^T + b_h2o
// Baseline: SIMT fp32 tiled GEMM, 128x128x16, double-buffered SMEM, 8x8/thread.

#define TM 128
#define TN 128
#define TK 16
#define PAD 4

#define B_DIM   8192
#define OBS_DIM 256
#define NH_DIM  2048
#define LAT_DIM 128

template<bool CONCAT, bool TANH>
__global__ __launch_bounds__(256, 2)
void rnn_gemm(const float* __restrict__ A0, int ldA0, int K0,
              const float* __restrict__ A1, int ldA1,
              const float* __restrict__ W,  int ldW,
              const float* __restrict__ bias,
              float* __restrict__ C, int ldC,
              int K)
{
    __shared__ float As[2][TK][TM + PAD];
    __shared__ float Bs[2][TK][TN + PAD];

    const int tid = threadIdx.x;
    const int tx = tid & 15;   // 0..15 -> N
    const int ty = tid >> 4;   // 0..15 -> M
    const int bm = blockIdx.y;
    const int bn = blockIdx.x;

    // global-load mapping: each thread owns rows r0 and r0+64, k-quad kq..kq+3
    const int r0 = tid >> 2;          // 0..63
    const int kq = (tid & 3) << 2;    // 0,4,8,12

    const size_t aRow0 = (size_t)bm * TM + r0;
    const size_t wRow0 = (size_t)bn * TN + r0;

    float4 rA0, rA1, rB0, rB1;
    const int nt = K / TK;

    auto gload = [&](int t) {
        const int kb = t * TK;
        const float* src; size_t ld; int col;
        if (CONCAT && kb >= K0) { src = A1; ld = (size_t)ldA1; col = kb - K0 + kq; }
        else                    { src = A0; ld = (size_t)ldA0; col = kb + kq; }
        rA0 = *(const float4*)(src + aRow0 * ld + col);
        rA1 = *(const float4*)(src + (aRow0 + 64) * ld + col);
        const float* wsrc = W + (size_t)kb + kq;
        rB0 = *(const float4*)(wsrc + wRow0 * (size_t)ldW);
        rB1 = *(const float4*)(wsrc + (wRow0 + 64) * (size_t)ldW);
    };
    auto sstore = [&](int buf) {
        As[buf][kq+0][r0]    = rA0.x; As[buf][kq+1][r0]    = rA0.y;
        As[buf][kq+2][r0]    = rA0.z; As[buf][kq+3][r0]    = rA0.w;
        As[buf][kq+0][r0+64] = rA1.x; As[buf][kq+1][r0+64] = rA1.y;
        As[buf][kq+2][r0+64] = rA1.z; As[buf][kq+3][r0+64] = rA1.w;
        Bs[buf][kq+0][r0]    = rB0.x; Bs[buf][kq+1][r0]    = rB0.y;
        Bs[buf][kq+2][r0]    = rB0.z; Bs[buf][kq+3][r0]    = rB0.w;
        Bs[buf][kq+0][r0+64] = rB1.x; Bs[buf][kq+1][r0+64] = rB1.y;
        Bs[buf][kq+2][r0+64] = rB1.z; Bs[buf][kq+3][r0+64] = rB1.w;
    };

    float acc[8][8];
    #pragma unroll
    for (int i = 0; i < 8; ++i)
        #pragma unroll
        for (int j = 0; j < 8; ++j) acc[i][j] = 0.0f;

    gload(0);
    sstore(0);
    __syncthreads();

    int buf = 0;
    for (int t = 0; t < nt; ++t) {
        if (t + 1 < nt) gload(t + 1);          // LDGs in flight during compute
        #pragma unroll
        for (int kk = 0; kk < TK; ++kk) {
            float a[8], b[8];
            *(float4*)&a[0] = *(const float4*)&As[buf][kk][ty * 4];
            *(float4*)&a[4] = *(const float4*)&As[buf][kk][64 + ty * 4];
            *(float4*)&b[0] = *(const float4*)&Bs[buf][kk][tx * 4];
            *(float4*)&b[4] = *(const float4*)&Bs[buf][kk][64 + tx * 4];
            #pragma unroll
            for (int i = 0; i < 8; ++i)
                #pragma unroll
                for (int j = 0; j < 8; ++j)
                    acc[i][j] = fmaf(a[i], b[j], acc[i][j]);
        }
        if (t + 1 < nt) sstore(buf ^ 1);       // buf^1 fully consumed >=1 sync ago
        __syncthreads();
        buf ^= 1;
    }

    // epilogue: bias (+tanh), float4 stores
    float bv[8];
    const int cn0 = bn * TN + tx * 4;
    #pragma unroll
    for (int j = 0; j < 4; ++j) {
        bv[j]     = bias[cn0 + j];
        bv[4 + j] = bias[cn0 + 64 + j];
    }

    #pragma unroll
    for (int i = 0; i < 8; ++i) {
        const size_t m = (size_t)bm * TM + ((i < 4) ? (ty * 4 + i) : (64 + ty * 4 + (i - 4)));
        float v[8];
        #pragma unroll
        for (int j = 0; j < 8; ++j) {
            float c = acc[i][j] + bv[j];
            v[j] = TANH ? tanhf(c) : c;
        }
        *(float4*)(C + m * (size_t)ldC + cn0)      = make_float4(v[0], v[1], v[2], v[3]);
        *(float4*)(C + m * (size_t)ldC + cn0 + 64) = make_float4(v[4], v[5], v[6], v[7]);
    }
}

extern "C" void kernel_launch(void* const* d_in, const int* in_sizes, int n_in,
                              void* d_out, int out_size) {
    const float* x  = (const float*)d_in[0];   // [8192, 256]
    const float* h  = (const float*)d_in[1];   // [8192, 2048]
    const float* W1 = (const float*)d_in[2];   // [2048, 2304]
    const float* b1 = (const float*)d_in[3];   // [2048]
    const float* W2 = (const float*)d_in[4];   // [256, 2048]
    const float* b2 = (const float*)d_in[5];   // [256]

    float* out  = (float*)d_out;                         // [8192, 256]
    float* hnew = out + (size_t)B_DIM * (2 * LAT_DIM);   // [8192, 2048]

    const int K1 = OBS_DIM + NH_DIM;  // 2304

    dim3 blk(256);
    // GEMM1: h_new = tanh(concat(x,h) @ W1^T + b1)   M=8192, N=2048, K=2304
    rnn_gemm<true,  true ><<<dim3(NH_DIM / TN, B_DIM / TM), blk>>>(
        x, OBS_DIM, OBS_DIM, h, NH_DIM, W1, K1, b1, hnew, NH_DIM, K1);
    // GEMM2: out = h_new @ W2^T + b2                 M=8192, N=256, K=2048
    rnn_gemm<false, false><<<dim3((2 * LAT_DIM) / TN, B_DIM / TM), blk>>>(
        hnew, NH_DIM, NH_DIM, nullptr, 0, W2, NH_DIM, b2, out, 2 * LAT_DIM, NH_DIM);
}

// round 3
// speedup vs baseline: 2.4084x; 2.4084x over previous
#include <cuda_runtime.h>
#include <cuda_bf16.h>
#include <math.h>
#include <stdint.h>

// Recognition_RNN via split-bf16 (hi/lo) mma.sync GEMMs (sm_103 target: no tcgen05).
//   h_new = tanh([x,h] @ W1^T + b1)   M=8192 N=2048 K=2304
//   out   = h_new  @ W2^T + b2        M=8192 N=256  K=2048
// fp32 = hi_bf16 + lo_bf16; product uses 3 cross terms on HMMA tensor cores.

#define B_DIM 8192
#define OBS   256
#define NHD   2048
#define LATD  128
#define KK1   (OBS + NHD)   // 2304
#define KK2   NHD           // 2048
#define NN1   NHD           // 2048
#define NN2   (2 * LATD)    // 256

// ---------------- scratch (bf16 hi/lo copies) ----------------
__device__ __align__(1024) __nv_bfloat16 g_Ahi[(size_t)B_DIM * KK1];
__device__ __align__(1024) __nv_bfloat16 g_Alo[(size_t)B_DIM * KK1];
__device__ __align__(1024) __nv_bfloat16 g_W1hi[(size_t)NN1 * KK1];
__device__ __align__(1024) __nv_bfloat16 g_W1lo[(size_t)NN1 * KK1];
__device__ __align__(1024) __nv_bfloat16 g_Hhi[(size_t)B_DIM * KK2];
__device__ __align__(1024) __nv_bfloat16 g_Hlo[(size_t)B_DIM * KK2];
__device__ __align__(1024) __nv_bfloat16 g_W2hi[(size_t)NN2 * KK2];
__device__ __align__(1024) __nv_bfloat16 g_W2lo[(size_t)NN2 * KK2];

// ---------------- PTX helpers ----------------
__device__ __forceinline__ uint32_t smem_u32(const void* p) {
    uint32_t a;
    asm("{ .reg .u64 t; cvta.to.shared.u64 t, %1; cvt.u32.u64 %0, t; }" : "=r"(a) : "l"(p));
    return a;
}
__device__ __forceinline__ void cp16(uint32_t s, const void* g) {
    asm volatile("cp.async.cg.shared.global [%0], [%1], 16;" :: "r"(s), "l"(g));
}
__device__ __forceinline__ void cp_commit() { asm volatile("cp.async.commit_group;" ::: "memory"); }
__device__ __forceinline__ void cp_wait1()  { asm volatile("cp.async.wait_group 1;" ::: "memory"); }
__device__ __forceinline__ void cp_wait0()  { asm volatile("cp.async.wait_group 0;" ::: "memory"); }

__device__ __forceinline__ void ldsm_x4(uint32_t& r0, uint32_t& r1, uint32_t& r2, uint32_t& r3,
                                        uint32_t addr) {
    asm volatile("ldmatrix.sync.aligned.m8n8.x4.shared.b16 {%0,%1,%2,%3}, [%4];"
                 : "=r"(r0), "=r"(r1), "=r"(r2), "=r"(r3) : "r"(addr));
}
__device__ __forceinline__ void mma_bf16(float* c, const uint32_t* a, const uint32_t* b) {
    asm volatile(
        "mma.sync.aligned.m16n8k16.row.col.f32.bf16.bf16.f32 "
        "{%0,%1,%2,%3}, {%4,%5,%6,%7}, {%8,%9}, {%0,%1,%2,%3};"
        : "+f"(c[0]), "+f"(c[1]), "+f"(c[2]), "+f"(c[3])
        : "r"(a[0]), "r"(a[1]), "r"(a[2]), "r"(a[3]), "r"(b[0]), "r"(b[1]));
}
__device__ __forceinline__ uint32_t swz(uint32_t off) { return off ^ ((off >> 3) & 0x70); }

// ---------------- prepass: fp32 -> (hi, lo) bf16 ----------------
__device__ __forceinline__ void split_store4(__nv_bfloat16* hp, __nv_bfloat16* lp, float4 v) {
    union { __nv_bfloat16 b[4]; uint2 u; } H, L;
    float f[4] = {v.x, v.y, v.z, v.w};
#pragma unroll
    for (int j = 0; j < 4; ++j) {
        __nv_bfloat16 hi = __float2bfloat16(f[j]);
        H.b[j] = hi;
        L.b[j] = __float2bfloat16(f[j] - __bfloat162float(hi));
    }
    *(uint2*)hp = H.u;
    *(uint2*)lp = L.u;
}

__global__ void k_split_concat(const float* __restrict__ x, const float* __restrict__ h) {
    size_t i = (size_t)blockIdx.x * blockDim.x + threadIdx.x;
    if (i >= (size_t)B_DIM * KK1 / 4) return;
    size_t e = i * 4;
    size_t row = e / KK1;
    int col = (int)(e % KK1);
    float4 v = (col < OBS) ? *(const float4*)(x + row * OBS + col)
                           : *(const float4*)(h + row * NHD + (col - OBS));
    split_store4(g_Ahi + e, g_Alo + e, v);
}

__global__ void k_split_w(const float* __restrict__ src, int which, size_t n4) {
    size_t i = (size_t)blockIdx.x * blockDim.x + threadIdx.x;
    if (i >= n4) return;
    size_t e = i * 4;
    __nv_bfloat16* hp = (which ? g_W2hi : g_W1hi) + e;
    __nv_bfloat16* lp = (which ? g_W2lo : g_W1lo) + e;
    split_store4(hp, lp, *(const float4*)(src + e));
}

// ---------------- tile loader: 128 rows x 128B, SW128 swizzled, cp.async ----------------
__device__ __forceinline__ void load_tile(uint32_t sdst, const __nv_bfloat16* __restrict__ g,
                                          size_t row0, int ld, int kc, int tid) {
#pragma unroll
    for (int i = 0; i < 4; ++i) {
        int op = i * 256 + tid;
        int r = op >> 3;
        int c = (op & 7) << 4;  // byte offset within 128B row
        const char* gp = (const char*)(g + (row0 + r) * (size_t)ld + kc) + c;
        cp16(sdst + swz((uint32_t)(r * 128 + c)), gp);
    }
}

// ---------------- main GEMM: CTA 128x128, K-chunk 64, 2-stage cp.async ----------------
// smem stage layout: Ahi @0, Alo @16K, Bhi @32K, Blo @48K; stage stride 64K.
template<bool FIRST>
__global__ __launch_bounds__(256, 1) void mm_gemm(const float* __restrict__ bias,
                                                  float* __restrict__ C) {
    constexpr int K      = FIRST ? KK1 : KK2;
    constexpr int LDC    = FIRST ? NN1 : NN2;
    constexpr int NTILES = K / 64;
    constexpr int STAGE  = 65536;

    const __nv_bfloat16* Ahi = FIRST ? g_Ahi : g_Hhi;
    const __nv_bfloat16* Alo = FIRST ? g_Alo : g_Hlo;
    const __nv_bfloat16* Bhi = FIRST ? g_W1hi : g_W2hi;
    const __nv_bfloat16* Blo = FIRST ? g_W1lo : g_W2lo;

    extern __shared__ unsigned char smem[];
    const uint32_t sb0 = smem_u32(smem);

    const int tid  = threadIdx.x;
    const int lane = tid & 31;
    const int wid  = tid >> 5;
    const int wm   = wid & 3;    // 4 warps along M -> 32 rows each
    const int wn   = wid >> 2;   // 2 warps along N -> 64 cols each
    const size_t m0 = (size_t)blockIdx.y * 128;
    const size_t n0 = (size_t)blockIdx.x * 128;

    float acc[2][8][4];
#pragma unroll
    for (int mt = 0; mt < 2; ++mt)
#pragma unroll
        for (int nt = 0; nt < 8; ++nt)
#pragma unroll
            for (int j = 0; j < 4; ++j) acc[mt][nt][j] = 0.0f;

    // per-lane base offsets within a 128x128B tile (pre-swizzle)
    const uint32_t a_off0 = (uint32_t)((wm * 32 + (lane & 15)) * 128 + (lane >> 4) * 16);
    const uint32_t b_off0 = (uint32_t)((wn * 64 + (lane & 15)) * 128 + (lane >> 4) * 16);

    // prologue: stages 0,1
#pragma unroll
    for (int s = 0; s < 2; ++s) {
        uint32_t sb = sb0 + s * STAGE;
        int kc = s * 64;
        load_tile(sb,          Ahi, m0, K, kc, tid);
        load_tile(sb + 16384,  Alo, m0, K, kc, tid);
        load_tile(sb + 32768,  Bhi, n0, K, kc, tid);
        load_tile(sb + 49152,  Blo, n0, K, kc, tid);
        cp_commit();
    }

    for (int t = 0; t < NTILES; ++t) {
        if (t + 1 < NTILES) cp_wait1(); else cp_wait0();
        __syncthreads();

        const uint32_t sb = sb0 + (t & 1) * STAGE;
#pragma unroll
        for (int ks = 0; ks < 4; ++ks) {
            const uint32_t kb = (uint32_t)(ks * 32);
            uint32_t ah[2][4], al[2][4];
#pragma unroll
            for (int mt = 0; mt < 2; ++mt) {
                uint32_t off = a_off0 + (uint32_t)(mt * 2048) + kb;
                ldsm_x4(ah[mt][0], ah[mt][1], ah[mt][2], ah[mt][3], sb + swz(off));
                ldsm_x4(al[mt][0], al[mt][1], al[mt][2], al[mt][3], sb + 16384 + swz(off));
            }
            uint32_t bh[8][2], bl[8][2];
#pragma unroll
            for (int p = 0; p < 4; ++p) {   // 16 n-rows per ldmatrix.x4 -> 2 frags
                uint32_t off = b_off0 + (uint32_t)(p * 2048) + kb;
                uint32_t r0, r1, r2, r3;
                ldsm_x4(r0, r1, r2, r3, sb + 32768 + swz(off));
                bh[p * 2][0] = r0; bh[p * 2][1] = r2;
                bh[p * 2 + 1][0] = r1; bh[p * 2 + 1][1] = r3;
                ldsm_x4(r0, r1, r2, r3, sb + 49152 + swz(off));
                bl[p * 2][0] = r0; bl[p * 2][1] = r2;
                bl[p * 2 + 1][0] = r1; bl[p * 2 + 1][1] = r3;
            }
#pragma unroll
            for (int mt = 0; mt < 2; ++mt)
#pragma unroll
                for (int nt = 0; nt < 8; ++nt) {
                    mma_bf16(acc[mt][nt], ah[mt], bh[nt]);   // hi*hi
                    mma_bf16(acc[mt][nt], ah[mt], bl[nt]);   // hi*lo
                    mma_bf16(acc[mt][nt], al[mt], bh[nt]);   // lo*hi
                }
        }
        __syncthreads();

        if (t + 2 < NTILES) {
            uint32_t lb = sb0 + (t & 1) * STAGE;
            int kc = (t + 2) * 64;
            load_tile(lb,          Ahi, m0, K, kc, tid);
            load_tile(lb + 16384,  Alo, m0, K, kc, tid);
            load_tile(lb + 32768,  Bhi, n0, K, kc, tid);
            load_tile(lb + 49152,  Blo, n0, K, kc, tid);
        }
        cp_commit();   // keep group count in lockstep even when empty
    }

    // ---------------- epilogue: bias (+tanh) (+hi/lo re-split of h_new) ----------------
#pragma unroll
    for (int mt = 0; mt < 2; ++mt) {
        const size_t gr0 = m0 + wm * 32 + mt * 16 + (lane >> 2);
#pragma unroll
        for (int nt = 0; nt < 8; ++nt) {
            const size_t n = n0 + wn * 64 + nt * 8 + (lane & 3) * 2;
            const float bv0 = bias[n], bv1 = bias[n + 1];
#pragma unroll
            for (int hlf = 0; hlf < 2; ++hlf) {
                const size_t r = gr0 + hlf * 8;
                float v0 = acc[mt][nt][hlf * 2 + 0] + bv0;
                float v1 = acc[mt][nt][hlf * 2 + 1] + bv1;
                if (FIRST) { v0 = tanhf(v0); v1 = tanhf(v1); }
                *(float2*)(C + r * (size_t)LDC + n) = make_float2(v0, v1);
                if (FIRST) {
                    __nv_bfloat16 h0 = __float2bfloat16(v0);
                    __nv_bfloat16 h1 = __float2bfloat16(v1);
                    __nv_bfloat16 l0 = __float2bfloat16(v0 - __bfloat162float(h0));
                    __nv_bfloat16 l1 = __float2bfloat16(v1 - __bfloat162float(h1));
                    union { __nv_bfloat16 b[2]; uint32_t u; } Hp, Lp;
                    Hp.b[0] = h0; Hp.b[1] = h1;
                    Lp.b[0] = l0; Lp.b[1] = l1;
                    *(uint32_t*)(g_Hhi + r * (size_t)KK2 + n) = Hp.u;
                    *(uint32_t*)(g_Hlo + r * (size_t)KK2 + n) = Lp.u;
                }
            }
        }
    }
}

// ---------------- launch ----------------
extern "C" void kernel_launch(void* const* d_in, const int* in_sizes, int n_in,
                              void* d_out, int out_size) {
    const float* x  = (const float*)d_in[0];
    const float* h  = (const float*)d_in[1];
    const float* W1 = (const float*)d_in[2];
    const float* b1 = (const float*)d_in[3];
    const float* W2 = (const float*)d_in[4];
    const float* b2 = (const float*)d_in[5];

    float* out  = (float*)d_out;                 // [8192, 256]
    float* hnew = out + (size_t)B_DIM * NN2;     // [8192, 2048]

    const int SMEM = 2 * 65536;  // 128 KB
    cudaFuncSetAttribute(mm_gemm<true>,  cudaFuncAttributeMaxDynamicSharedMemorySize, SMEM);
    cudaFuncSetAttribute(mm_gemm<false>, cudaFuncAttributeMaxDynamicSharedMemorySize, SMEM);

    const size_t nA  = (size_t)B_DIM * KK1 / 4;
    const size_t nW1 = (size_t)NN1 * KK1 / 4;
    const size_t nW2 = (size_t)NN2 * KK2 / 4;
    k_split_concat<<<(unsigned)((nA + 255) / 256), 256>>>(x, h);
    k_split_w<<<(unsigned)((nW1 + 255) / 256), 256>>>(W1, 0, nW1);
    k_split_w<<<(unsigned)((nW2 + 255) / 256), 256>>>(W2, 1, nW2);

    mm_gemm<true ><<<dim3(NN1 / 128, B_DIM / 128), 256, SMEM>>>(b1, hnew);
    mm_gemm<false><<<dim3(NN2 / 128, B_DIM / 128), 256, SMEM>>>(b2, out);
}

// round 4
// speedup vs baseline: 3.3856x; 1.4058x over previous
#include <cuda_runtime.h>
#include <cuda_fp16.h>
#include <math.h>
#include <stdint.h>

// Recognition_RNN via split-fp16 mma.sync GEMMs (sm_103 target: no tcgen05).
//   GEMM1: h_new = tanh([x,h] @ W1^T + b1)  M=8192 N=2048 K=2304
//          2-term: (Ahi+Alo) @ W1hi   (W1 fp16-quantized; rel err ~2.8e-4)
//   GEMM2: out = h_new @ W2^T + b2          M=8192 N=256 K=2048
//          3-term: Hhi*W2hi + Hhi*W2lo + Hlo*W2hi  (near-fp32)

#define B_DIM 8192
#define OBS   256
#define NHD   2048
#define LATD  128
#define KK1   (OBS + NHD)   // 2304
#define KK2   NHD           // 2048
#define NN1   NHD           // 2048
#define NN2   (2 * LATD)    // 256

// ---------------- scratch (fp16 copies) ----------------
__device__ __align__(1024) __half g_Ahi[(size_t)B_DIM * KK1];
__device__ __align__(1024) __half g_Alo[(size_t)B_DIM * KK1];
__device__ __align__(1024) __half g_W1hi[(size_t)NN1 * KK1];
__device__ __align__(1024) __half g_Hhi[(size_t)B_DIM * KK2];
__device__ __align__(1024) __half g_Hlo[(size_t)B_DIM * KK2];
__device__ __align__(1024) __half g_W2hi[(size_t)NN2 * KK2];
__device__ __align__(1024) __half g_W2lo[(size_t)NN2 * KK2];

// ---------------- PTX helpers ----------------
__device__ __forceinline__ uint32_t smem_u32(const void* p) {
    uint32_t a;
    asm("{ .reg .u64 t; cvta.to.shared.u64 t, %1; cvt.u32.u64 %0, t; }" : "=r"(a) : "l"(p));
    return a;
}
__device__ __forceinline__ void cp16(uint32_t s, const void* g) {
    asm volatile("cp.async.cg.shared.global [%0], [%1], 16;" :: "r"(s), "l"(g));
}
__device__ __forceinline__ void cp_commit() { asm volatile("cp.async.commit_group;" ::: "memory"); }
__device__ __forceinline__ void cp_wait1()  { asm volatile("cp.async.wait_group 1;" ::: "memory"); }
__device__ __forceinline__ void cp_wait0()  { asm volatile("cp.async.wait_group 0;" ::: "memory"); }

__device__ __forceinline__ void ldsm_x4(uint32_t& r0, uint32_t& r1, uint32_t& r2, uint32_t& r3,
                                        uint32_t addr) {
    asm volatile("ldmatrix.sync.aligned.m8n8.x4.shared.b16 {%0,%1,%2,%3}, [%4];"
                 : "=r"(r0), "=r"(r1), "=r"(r2), "=r"(r3) : "r"(addr));
}
__device__ __forceinline__ void mma_fp16(float* c, const uint32_t* a, const uint32_t* b) {
    asm volatile(
        "mma.sync.aligned.m16n8k16.row.col.f32.f16.f16.f32 "
        "{%0,%1,%2,%3}, {%4,%5,%6,%7}, {%8,%9}, {%0,%1,%2,%3};"
        : "+f"(c[0]), "+f"(c[1]), "+f"(c[2]), "+f"(c[3])
        : "r"(a[0]), "r"(a[1]), "r"(a[2]), "r"(a[3]), "r"(b[0]), "r"(b[1]));
}
__device__ __forceinline__ uint32_t swz(uint32_t off) { return off ^ ((off >> 3) & 0x70); }

// ---------------- prepass: fp32 -> (hi, lo) fp16 ----------------
__device__ __forceinline__ void split_store4(__half* hp, __half* lp, float4 v) {
    union { __half b[4]; uint2 u; } H, L;
    float f[4] = {v.x, v.y, v.z, v.w};
#pragma unroll
    for (int j = 0; j < 4; ++j) {
        __half hi = __float2half_rn(f[j]);
        H.b[j] = hi;
        L.b[j] = __float2half_rn(f[j] - __half2float(hi));
    }
    *(uint2*)hp = H.u;
    *(uint2*)lp = L.u;
}
__device__ __forceinline__ void hi_store4(__half* hp, float4 v) {
    union { __half b[4]; uint2 u; } H;
    H.b[0] = __float2half_rn(v.x); H.b[1] = __float2half_rn(v.y);
    H.b[2] = __float2half_rn(v.z); H.b[3] = __float2half_rn(v.w);
    *(uint2*)hp = H.u;
}

__global__ void k_split_concat(const float* __restrict__ x, const float* __restrict__ h) {
    size_t i = (size_t)blockIdx.x * blockDim.x + threadIdx.x;
    if (i >= (size_t)B_DIM * KK1 / 4) return;
    size_t e = i * 4;
    size_t row = e / KK1;
    int col = (int)(e % KK1);
    float4 v = (col < OBS) ? *(const float4*)(x + row * OBS + col)
                           : *(const float4*)(h + row * NHD + (col - OBS));
    split_store4(g_Ahi + e, g_Alo + e, v);
}

__global__ void k_quant_w1(const float* __restrict__ src, size_t n4) {
    size_t i = (size_t)blockIdx.x * blockDim.x + threadIdx.x;
    if (i >= n4) return;
    size_t e = i * 4;
    hi_store4(g_W1hi + e, *(const float4*)(src + e));
}

__global__ void k_split_w2(const float* __restrict__ src, size_t n4) {
    size_t i = (size_t)blockIdx.x * blockDim.x + threadIdx.x;
    if (i >= n4) return;
    size_t e = i * 4;
    split_store4(g_W2hi + e, g_W2lo + e, *(const float4*)(src + e));
}

// ---------------- tile loader: 128 rows x 128B, SW128 swizzled, cp.async ----------------
__device__ __forceinline__ void load_tile(uint32_t sdst, const __half* __restrict__ g,
                                          size_t row0, int ld, int kc, int tid) {
#pragma unroll
    for (int i = 0; i < 4; ++i) {
        int op = i * 256 + tid;
        int r = op >> 3;
        int c = (op & 7) << 4;  // byte offset within 128B row
        const char* gp = (const char*)(g + (row0 + r) * (size_t)ld + kc) + c;
        cp16(sdst + swz((uint32_t)(r * 128 + c)), gp);
    }
}

// ---------------- main GEMM: CTA 128x128, K-chunk 64, 2-stage cp.async ----------------
// FIRST (GEMM1): stage = Ahi@0, Alo@16K, Bhi@32K -> 48KB/stage, 2 CTAs/SM
// !FIRST (GEMM2): stage = Ahi@0, Alo@16K, Bhi@32K, Blo@48K -> 64KB/stage
template<bool FIRST>
__global__ __launch_bounds__(256, FIRST ? 2 : 1)
void mm_gemm(const float* __restrict__ bias, float* __restrict__ C) {
    constexpr int K      = FIRST ? KK1 : KK2;
    constexpr int LDC    = FIRST ? NN1 : NN2;
    constexpr int NTILES = K / 64;
    constexpr int STAGE  = FIRST ? 49152 : 65536;

    const __half* Ahi = FIRST ? g_Ahi : g_Hhi;
    const __half* Alo = FIRST ? g_Alo : g_Hlo;
    const __half* Bhi = FIRST ? g_W1hi : g_W2hi;
    const __half* Blo = FIRST ? (const __half*)nullptr : g_W2lo;

    extern __shared__ unsigned char smem[];
    const uint32_t sb0 = smem_u32(smem);

    const int tid  = threadIdx.x;
    const int lane = tid & 31;
    const int wid  = tid >> 5;
    const int wm   = wid & 3;    // 4 warps along M -> 32 rows each
    const int wn   = wid >> 2;   // 2 warps along N -> 64 cols each
    const size_t m0 = (size_t)blockIdx.y * 128;
    const size_t n0 = (size_t)blockIdx.x * 128;

    float acc[2][8][4];
#pragma unroll
    for (int mt = 0; mt < 2; ++mt)
#pragma unroll
        for (int nt = 0; nt < 8; ++nt)
#pragma unroll
            for (int j = 0; j < 4; ++j) acc[mt][nt][j] = 0.0f;

    const uint32_t a_off0 = (uint32_t)((wm * 32 + (lane & 15)) * 128 + (lane >> 4) * 16);
    const uint32_t b_off0 = (uint32_t)((wn * 64 + (lane & 15)) * 128 + (lane >> 4) * 16);

    // prologue: stages 0,1
#pragma unroll
    for (int s = 0; s < 2; ++s) {
        uint32_t sb = sb0 + s * STAGE;
        int kc = s * 64;
        load_tile(sb,         Ahi, m0, K, kc, tid);
        load_tile(sb + 16384, Alo, m0, K, kc, tid);
        load_tile(sb + 32768, Bhi, n0, K, kc, tid);
        if (!FIRST) load_tile(sb + 49152, Blo, n0, K, kc, tid);
        cp_commit();
    }

    for (int t = 0; t < NTILES; ++t) {
        if (t + 1 < NTILES) cp_wait1(); else cp_wait0();
        __syncthreads();

        const uint32_t sb = sb0 + (t & 1) * STAGE;
#pragma unroll
        for (int ks = 0; ks < 4; ++ks) {
            const uint32_t kb = (uint32_t)(ks * 32);
            uint32_t ah[2][4], al[2][4];
#pragma unroll
            for (int mt = 0; mt < 2; ++mt) {
                uint32_t off = a_off0 + (uint32_t)(mt * 2048) + kb;
                ldsm_x4(ah[mt][0], ah[mt][1], ah[mt][2], ah[mt][3], sb + swz(off));
                ldsm_x4(al[mt][0], al[mt][1], al[mt][2], al[mt][3], sb + 16384 + swz(off));
            }
            uint32_t bh[8][2], bl[8][2];
#pragma unroll
            for (int p = 0; p < 4; ++p) {   // 16 n-rows per ldmatrix.x4 -> 2 frags
                uint32_t off = b_off0 + (uint32_t)(p * 2048) + kb;
                uint32_t r0, r1, r2, r3;
                ldsm_x4(r0, r1, r2, r3, sb + 32768 + swz(off));
                bh[p * 2][0] = r0; bh[p * 2][1] = r2;
                bh[p * 2 + 1][0] = r1; bh[p * 2 + 1][1] = r3;
                if (!FIRST) {
                    ldsm_x4(r0, r1, r2, r3, sb + 49152 + swz(off));
                    bl[p * 2][0] = r0; bl[p * 2][1] = r2;
                    bl[p * 2 + 1][0] = r1; bl[p * 2 + 1][1] = r3;
                }
            }
#pragma unroll
            for (int mt = 0; mt < 2; ++mt)
#pragma unroll
                for (int nt = 0; nt < 8; ++nt) {
                    mma_fp16(acc[mt][nt], ah[mt], bh[nt]);       // hi*hi
                    mma_fp16(acc[mt][nt], al[mt], bh[nt]);       // lo*hi
                    if (!FIRST) mma_fp16(acc[mt][nt], ah[mt], bl[nt]);  // hi*lo
                }
        }
        __syncthreads();

        if (t + 2 < NTILES) {
            uint32_t lb = sb0 + (t & 1) * STAGE;
            int kc = (t + 2) * 64;
            load_tile(lb,         Ahi, m0, K, kc, tid);
            load_tile(lb + 16384, Alo, m0, K, kc, tid);
            load_tile(lb + 32768, Bhi, n0, K, kc, tid);
            if (!FIRST) load_tile(lb + 49152, Blo, n0, K, kc, tid);
        }
        cp_commit();   // keep group count in lockstep even when empty
    }

    // ---------------- epilogue: bias (+tanh) (+hi/lo re-split of h_new) ----------------
#pragma unroll
    for (int mt = 0; mt < 2; ++mt) {
        const size_t gr0 = m0 + wm * 32 + mt * 16 + (lane >> 2);
#pragma unroll
        for (int nt = 0; nt < 8; ++nt) {
            const size_t n = n0 + wn * 64 + nt * 8 + (lane & 3) * 2;
            const float bv0 = bias[n], bv1 = bias[n + 1];
#pragma unroll
            for (int hlf = 0; hlf < 2; ++hlf) {
                const size_t r = gr0 + hlf * 8;
                float v0 = acc[mt][nt][hlf * 2 + 0] + bv0;
                float v1 = acc[mt][nt][hlf * 2 + 1] + bv1;
                if (FIRST) { v0 = tanhf(v0); v1 = tanhf(v1); }
                *(float2*)(C + r * (size_t)LDC + n) = make_float2(v0, v1);
                if (FIRST) {
                    __half h0 = __float2half_rn(v0);
                    __half h1 = __float2half_rn(v1);
                    __half l0 = __float2half_rn(v0 - __half2float(h0));
                    __half l1 = __float2half_rn(v1 - __half2float(h1));
                    union { __half b[2]; uint32_t u; } Hp, Lp;
                    Hp.b[0] = h0; Hp.b[1] = h1;
                    Lp.b[0] = l0; Lp.b[1] = l1;
                    *(uint32_t*)(g_Hhi + r * (size_t)KK2 + n) = Hp.u;
                    *(uint32_t*)(g_Hlo + r * (size_t)KK2 + n) = Lp.u;
                }
            }
        }
    }
}

// ---------------- launch ----------------
extern "C" void kernel_launch(void* const* d_in, const int* in_sizes, int n_in,
                              void* d_out, int out_size) {
    const float* x  = (const float*)d_in[0];
    const float* h  = (const float*)d_in[1];
    const float* W1 = (const float*)d_in[2];
    const float* b1 = (const float*)d_in[3];
    const float* W2 = (const float*)d_in[4];
    const float* b2 = (const float*)d_in[5];

    float* out  = (float*)d_out;                 // [8192, 256]
    float* hnew = out + (size_t)B_DIM * NN2;     // [8192, 2048]

    const int SMEM1 = 2 * 49152;  // 96 KB  -> 2 CTAs/SM
    const int SMEM2 = 2 * 65536;  // 128 KB -> 1 CTA/SM
    cudaFuncSetAttribute(mm_gemm<true>,  cudaFuncAttributeMaxDynamicSharedMemorySize, SMEM1);
    cudaFuncSetAttribute(mm_gemm<false>, cudaFuncAttributeMaxDynamicSharedMemorySize, SMEM2);

    const size_t nA  = (size_t)B_DIM * KK1 / 4;
    const size_t nW1 = (size_t)NN1 * KK1 / 4;
    const size_t nW2 = (size_t)NN2 * KK2 / 4;
    k_split_concat<<<(unsigned)((nA + 255) / 256), 256>>>(x, h);
    k_quant_w1<<<(unsigned)((nW1 + 255) / 256), 256>>>(W1, nW1);
    k_split_w2<<<(unsigned)((nW2 + 255) / 256), 256>>>(W2, nW2);

    mm_gemm<true ><<<dim3(NN1 / 128, B_DIM / 128), 256, SMEM1>>>(b1, hnew);
    mm_gemm<false><<<dim3(NN2 / 128, B_DIM / 128), 256, SMEM2>>>(b2, out);
}

// round 5
// speedup vs baseline: 5.3059x; 1.5672x over previous
#include <cuda_runtime.h>
#include <cuda_fp16.h>
#include <math.h>
#include <stdint.h>

// Recognition_RNN via fp16 mma.sync GEMMs (sm_103 target: no tcgen05).
//   GEMM1: h_new = tanh([x,h] @ W1^T + b1)  M=8192 N=2048 K=2304
//          1-term: Ahi @ W1hi (both fp16-quantized; rel err ~3.2e-4)
//   GEMM2: out = h_new @ W2^T + b2          M=8192 N=256 K=2048
//          3-term: Hhi*W2hi + Hhi*W2lo + Hlo*W2hi  (near-fp32)

#define B_DIM 8192
#define OBS   256
#define NHD   2048
#define LATD  128
#define KK1   (OBS + NHD)   // 2304
#define KK2   NHD           // 2048
#define NN1   NHD           // 2048
#define NN2   (2 * LATD)    // 256

// ---------------- scratch (fp16 copies) ----------------
__device__ __align__(1024) __half g_Ahi[(size_t)B_DIM * KK1];
__device__ __align__(1024) __half g_W1hi[(size_t)NN1 * KK1];
__device__ __align__(1024) __half g_Hhi[(size_t)B_DIM * KK2];
__device__ __align__(1024) __half g_Hlo[(size_t)B_DIM * KK2];
__device__ __align__(1024) __half g_W2hi[(size_t)NN2 * KK2];
__device__ __align__(1024) __half g_W2lo[(size_t)NN2 * KK2];

// ---------------- PTX helpers ----------------
__device__ __forceinline__ uint32_t smem_u32(const void* p) {
    uint32_t a;
    asm("{ .reg .u64 t; cvta.to.shared.u64 t, %1; cvt.u32.u64 %0, t; }" : "=r"(a) : "l"(p));
    return a;
}
__device__ __forceinline__ void cp16(uint32_t s, const void* g) {
    asm volatile("cp.async.cg.shared.global [%0], [%1], 16;" :: "r"(s), "l"(g));
}
__device__ __forceinline__ void cp_commit() { asm volatile("cp.async.commit_group;" ::: "memory"); }
__device__ __forceinline__ void cp_wait1()  { asm volatile("cp.async.wait_group 1;" ::: "memory"); }
__device__ __forceinline__ void cp_wait0()  { asm volatile("cp.async.wait_group 0;" ::: "memory"); }

__device__ __forceinline__ void ldsm_x4(uint32_t& r0, uint32_t& r1, uint32_t& r2, uint32_t& r3,
                                        uint32_t addr) {
    asm volatile("ldmatrix.sync.aligned.m8n8.x4.shared.b16 {%0,%1,%2,%3}, [%4];"
                 : "=r"(r0), "=r"(r1), "=r"(r2), "=r"(r3) : "r"(addr));
}
__device__ __forceinline__ void mma_fp16(float* c, const uint32_t* a, const uint32_t* b) {
    asm volatile(
        "mma.sync.aligned.m16n8k16.row.col.f32.f16.f16.f32 "
        "{%0,%1,%2,%3}, {%4,%5,%6,%7}, {%8,%9}, {%0,%1,%2,%3};"
        : "+f"(c[0]), "+f"(c[1]), "+f"(c[2]), "+f"(c[3])
        : "r"(a[0]), "r"(a[1]), "r"(a[2]), "r"(a[3]), "r"(b[0]), "r"(b[1]));
}
__device__ __forceinline__ uint32_t swz(uint32_t off) { return off ^ ((off >> 3) & 0x70); }

// ---------------- prepass ----------------
__device__ __forceinline__ void split_store4(__half* hp, __half* lp, float4 v) {
    union { __half b[4]; uint2 u; } H, L;
    float f[4] = {v.x, v.y, v.z, v.w};
#pragma unroll
    for (int j = 0; j < 4; ++j) {
        __half hi = __float2half_rn(f[j]);
        H.b[j] = hi;
        L.b[j] = __float2half_rn(f[j] - __half2float(hi));
    }
    *(uint2*)hp = H.u;
    *(uint2*)lp = L.u;
}
__device__ __forceinline__ void hi_store4(__half* hp, float4 v) {
    union { __half b[4]; uint2 u; } H;
    H.b[0] = __float2half_rn(v.x); H.b[1] = __float2half_rn(v.y);
    H.b[2] = __float2half_rn(v.z); H.b[3] = __float2half_rn(v.w);
    *(uint2*)hp = H.u;
}

__global__ void k_cat_hi(const float* __restrict__ x, const float* __restrict__ h) {
    size_t i = (size_t)blockIdx.x * blockDim.x + threadIdx.x;
    if (i >= (size_t)B_DIM * KK1 / 4) return;
    size_t e = i * 4;
    size_t row = e / KK1;
    int col = (int)(e % KK1);
    float4 v = (col < OBS) ? *(const float4*)(x + row * OBS + col)
                           : *(const float4*)(h + row * NHD + (col - OBS));
    hi_store4(g_Ahi + e, v);
}
__global__ void k_quant_w1(const float* __restrict__ src, size_t n4) {
    size_t i = (size_t)blockIdx.x * blockDim.x + threadIdx.x;
    if (i >= n4) return;
    size_t e = i * 4;
    hi_store4(g_W1hi + e, *(const float4*)(src + e));
}
__global__ void k_split_w2(const float* __restrict__ src, size_t n4) {
    size_t i = (size_t)blockIdx.x * blockDim.x + threadIdx.x;
    if (i >= n4) return;
    size_t e = i * 4;
    split_store4(g_W2hi + e, g_W2lo + e, *(const float4*)(src + e));
}

// ---------------- tile loader: ROWS x 128B, SW128 swizzled, cp.async ----------------
template<int ROWS>
__device__ __forceinline__ void load_tile(uint32_t sdst, const __half* __restrict__ g,
                                          size_t row0, int ld, int kc, int tid) {
#pragma unroll
    for (int i = 0; i < ROWS / 32; ++i) {
        int op = i * 256 + tid;
        int r = op >> 3;
        int c = (op & 7) << 4;
        const char* gp = (const char*)(g + (row0 + r) * (size_t)ld + kc) + c;
        cp16(sdst + swz((uint32_t)(r * 128 + c)), gp);
    }
}

// ================= GEMM1: 1-term, CTA 128x128, 3-stage, 1 sync/tile =================
// stage = Ahi@0 (16K) + Bhi@16K (16K) = 32KB; 3 stages = 96KB; 2 CTAs/SM
__global__ __launch_bounds__(256, 2)
void g1_gemm(const float* __restrict__ bias, float* __restrict__ C) {
    constexpr int NTILES = KK1 / 64;   // 36
    constexpr int STAGE  = 32768;

    extern __shared__ unsigned char smem[];
    const uint32_t sb0 = smem_u32(smem);

    const int tid  = threadIdx.x;
    const int lane = tid & 31;
    const int wid  = tid >> 5;
    const int wm   = wid & 3;
    const int wn   = wid >> 2;
    const size_t m0 = (size_t)blockIdx.y * 128;
    const size_t n0 = (size_t)blockIdx.x * 128;

    float acc[2][8][4];
#pragma unroll
    for (int mt = 0; mt < 2; ++mt)
#pragma unroll
        for (int nt = 0; nt < 8; ++nt)
#pragma unroll
            for (int j = 0; j < 4; ++j) acc[mt][nt][j] = 0.0f;

    const uint32_t a_off0 = (uint32_t)((wm * 32 + (lane & 15)) * 128 + (lane >> 4) * 16);
    const uint32_t b_off0 = (uint32_t)((wn * 64 + (lane & 15)) * 128 + (lane >> 4) * 16);
    // precomputed swizzled offsets; inner loop uses (asw ^ kb) -- valid since off bits[5:6]=0
    uint32_t asw[2], bsw[4];
#pragma unroll
    for (int mt = 0; mt < 2; ++mt) asw[mt] = swz(a_off0 + mt * 2048);
#pragma unroll
    for (int p = 0; p < 4; ++p) bsw[p] = swz(b_off0 + p * 2048);

    // prologue: stages 0,1
#pragma unroll
    for (int s = 0; s < 2; ++s) {
        uint32_t sb = sb0 + s * STAGE;
        load_tile<128>(sb,         g_Ahi,  m0, KK1, s * 64, tid);
        load_tile<128>(sb + 16384, g_W1hi, n0, KK1, s * 64, tid);
        cp_commit();
    }

    int sc = 0, sl = 2;
    for (int t = 0; t < NTILES; ++t) {
        cp_wait1();
        __syncthreads();

        // issue loads for t+2 into buffer finished two tiles ago
        if (t + 2 < NTILES) {
            uint32_t lb = sb0 + sl * STAGE;
            int kc = (t + 2) * 64;
            load_tile<128>(lb,         g_Ahi,  m0, KK1, kc, tid);
            load_tile<128>(lb + 16384, g_W1hi, n0, KK1, kc, tid);
        }
        cp_commit();

        const uint32_t sbA = sb0 + sc * STAGE;
        const uint32_t sbB = sbA + 16384;
#pragma unroll
        for (int ks = 0; ks < 4; ++ks) {
            const uint32_t kb = (uint32_t)(ks * 32);
            uint32_t ah[2][4];
#pragma unroll
            for (int mt = 0; mt < 2; ++mt)
                ldsm_x4(ah[mt][0], ah[mt][1], ah[mt][2], ah[mt][3], sbA + (asw[mt] ^ kb));
            uint32_t bh[8][2];
#pragma unroll
            for (int p = 0; p < 4; ++p) {
                uint32_t r0, r1, r2, r3;
                ldsm_x4(r0, r1, r2, r3, sbB + (bsw[p] ^ kb));
                bh[p * 2][0] = r0; bh[p * 2][1] = r2;
                bh[p * 2 + 1][0] = r1; bh[p * 2 + 1][1] = r3;
            }
#pragma unroll
            for (int mt = 0; mt < 2; ++mt)
#pragma unroll
                for (int nt = 0; nt < 8; ++nt)
                    mma_fp16(acc[mt][nt], ah[mt], bh[nt]);
        }
        sc = (sc == 2) ? 0 : sc + 1;
        sl = (sl == 2) ? 0 : sl + 1;
    }

    // epilogue: bias + tanh + fp32 store + hi/lo re-split for GEMM2
#pragma unroll
    for (int mt = 0; mt < 2; ++mt) {
        const size_t gr0 = m0 + wm * 32 + mt * 16 + (lane >> 2);
#pragma unroll
        for (int nt = 0; nt < 8; ++nt) {
            const size_t n = n0 + wn * 64 + nt * 8 + (lane & 3) * 2;
            const float bv0 = bias[n], bv1 = bias[n + 1];
#pragma unroll
            for (int hlf = 0; hlf < 2; ++hlf) {
                const size_t r = gr0 + hlf * 8;
                float v0 = tanhf(acc[mt][nt][hlf * 2 + 0] + bv0);
                float v1 = tanhf(acc[mt][nt][hlf * 2 + 1] + bv1);
                *(float2*)(C + r * (size_t)NN1 + n) = make_float2(v0, v1);
                __half h0 = __float2half_rn(v0);
                __half h1 = __float2half_rn(v1);
                __half l0 = __float2half_rn(v0 - __half2float(h0));
                __half l1 = __float2half_rn(v1 - __half2float(h1));
                union { __half b[2]; uint32_t u; } Hp, Lp;
                Hp.b[0] = h0; Hp.b[1] = h1;
                Lp.b[0] = l0; Lp.b[1] = l1;
                *(uint32_t*)(g_Hhi + r * (size_t)KK2 + n) = Hp.u;
                *(uint32_t*)(g_Hlo + r * (size_t)KK2 + n) = Lp.u;
            }
        }
    }
}

// ================= GEMM2: 3-term, CTA 128x64, 2-stage =================
// stage = Ahi@0 (16K), Alo@16K (16K), Bhi@32K (8K), Blo@40K (8K) = 48KB; 2 CTAs/SM
__global__ __launch_bounds__(256, 2)
void g2_gemm(const float* __restrict__ bias, float* __restrict__ C) {
    constexpr int NTILES = KK2 / 64;   // 32
    constexpr int STAGE  = 49152;

    extern __shared__ unsigned char smem[];
    const uint32_t sb0 = smem_u32(smem);

    const int tid  = threadIdx.x;
    const int lane = tid & 31;
    const int wid  = tid >> 5;
    const int wm   = wid & 3;
    const int wn   = wid >> 2;   // 0..1
    const size_t m0 = (size_t)blockIdx.y * 128;
    const size_t n0 = (size_t)blockIdx.x * 64;

    float acc[2][4][4];
#pragma unroll
    for (int mt = 0; mt < 2; ++mt)
#pragma unroll
        for (int nt = 0; nt < 4; ++nt)
#pragma unroll
            for (int j = 0; j < 4; ++j) acc[mt][nt][j] = 0.0f;

    const uint32_t a_off0 = (uint32_t)((wm * 32 + (lane & 15)) * 128 + (lane >> 4) * 16);
    const uint32_t b_off0 = (uint32_t)((wn * 32 + (lane & 15)) * 128 + (lane >> 4) * 16);
    uint32_t asw[2], bsw[2];
#pragma unroll
    for (int mt = 0; mt < 2; ++mt) asw[mt] = swz(a_off0 + mt * 2048);
#pragma unroll
    for (int p = 0; p < 2; ++p) bsw[p] = swz(b_off0 + p * 2048);

#pragma unroll
    for (int s = 0; s < 2; ++s) {
        uint32_t sb = sb0 + s * STAGE;
        int kc = s * 64;
        load_tile<128>(sb,         g_Hhi,  m0, KK2, kc, tid);
        load_tile<128>(sb + 16384, g_Hlo,  m0, KK2, kc, tid);
        load_tile<64 >(sb + 32768, g_W2hi, n0, KK2, kc, tid);
        load_tile<64 >(sb + 40960, g_W2lo, n0, KK2, kc, tid);
        cp_commit();
    }

    for (int t = 0; t < NTILES; ++t) {
        if (t + 1 < NTILES) cp_wait1(); else cp_wait0();
        __syncthreads();

        const uint32_t sb = sb0 + (t & 1) * STAGE;
#pragma unroll
        for (int ks = 0; ks < 4; ++ks) {
            const uint32_t kb = (uint32_t)(ks * 32);
            uint32_t ah[2][4], al[2][4];
#pragma unroll
            for (int mt = 0; mt < 2; ++mt) {
                ldsm_x4(ah[mt][0], ah[mt][1], ah[mt][2], ah[mt][3], sb + (asw[mt] ^ kb));
                ldsm_x4(al[mt][0], al[mt][1], al[mt][2], al[mt][3], sb + 16384 + (asw[mt] ^ kb));
            }
            uint32_t bh[4][2], bl[4][2];
#pragma unroll
            for (int p = 0; p < 2; ++p) {
                uint32_t r0, r1, r2, r3;
                ldsm_x4(r0, r1, r2, r3, sb + 32768 + (bsw[p] ^ kb));
                bh[p * 2][0] = r0; bh[p * 2][1] = r2;
                bh[p * 2 + 1][0] = r1; bh[p * 2 + 1][1] = r3;
                ldsm_x4(r0, r1, r2, r3, sb + 40960 + (bsw[p] ^ kb));
                bl[p * 2][0] = r0; bl[p * 2][1] = r2;
                bl[p * 2 + 1][0] = r1; bl[p * 2 + 1][1] = r3;
            }
#pragma unroll
            for (int mt = 0; mt < 2; ++mt)
#pragma unroll
                for (int nt = 0; nt < 4; ++nt) {
                    mma_fp16(acc[mt][nt], ah[mt], bh[nt]);
                    mma_fp16(acc[mt][nt], al[mt], bh[nt]);
                    mma_fp16(acc[mt][nt], ah[mt], bl[nt]);
                }
        }
        __syncthreads();

        if (t + 2 < NTILES) {
            uint32_t lb = sb0 + (t & 1) * STAGE;
            int kc = (t + 2) * 64;
            load_tile<128>(lb,         g_Hhi,  m0, KK2, kc, tid);
            load_tile<128>(lb + 16384, g_Hlo,  m0, KK2, kc, tid);
            load_tile<64 >(lb + 32768, g_W2hi, n0, KK2, kc, tid);
            load_tile<64 >(lb + 40960, g_W2lo, n0, KK2, kc, tid);
        }
        cp_commit();
    }

#pragma unroll
    for (int mt = 0; mt < 2; ++mt) {
        const size_t gr0 = m0 + wm * 32 + mt * 16 + (lane >> 2);
#pragma unroll
        for (int nt = 0; nt < 4; ++nt) {
            const size_t n = n0 + wn * 32 + nt * 8 + (lane & 3) * 2;
            const float bv0 = bias[n], bv1 = bias[n + 1];
#pragma unroll
            for (int hlf = 0; hlf < 2; ++hlf) {
                const size_t r = gr0 + hlf * 8;
                float v0 = acc[mt][nt][hlf * 2 + 0] + bv0;
                float v1 = acc[mt][nt][hlf * 2 + 1] + bv1;
                *(float2*)(C + r * (size_t)NN2 + n) = make_float2(v0, v1);
            }
        }
    }
}

// ---------------- launch ----------------
extern "C" void kernel_launch(void* const* d_in, const int* in_sizes, int n_in,
                              void* d_out, int out_size) {
    const float* x  = (const float*)d_in[0];
    const float* h  = (const float*)d_in[1];
    const float* W1 = (const float*)d_in[2];
    const float* b1 = (const float*)d_in[3];
    const float* W2 = (const float*)d_in[4];
    const float* b2 = (const float*)d_in[5];

    float* out  = (float*)d_out;                 // [8192, 256]
    float* hnew = out + (size_t)B_DIM * NN2;     // [8192, 2048]

    const int SMEM1 = 3 * 32768;  // 96 KB -> 2 CTAs/SM
    const int SMEM2 = 2 * 49152;  // 96 KB -> 2 CTAs/SM
    cudaFuncSetAttribute(g1_gemm, cudaFuncAttributeMaxDynamicSharedMemorySize, SMEM1);
    cudaFuncSetAttribute(g2_gemm, cudaFuncAttributeMaxDynamicSharedMemorySize, SMEM2);

    const size_t nA  = (size_t)B_DIM * KK1 / 4;
    const size_t nW1 = (size_t)NN1 * KK1 / 4;
    const size_t nW2 = (size_t)NN2 * KK2 / 4;
    k_cat_hi<<<(unsigned)((nA + 255) / 256), 256>>>(x, h);
    k_quant_w1<<<(unsigned)((nW1 + 255) / 256), 256>>>(W1, nW1);
    k_split_w2<<<(unsigned)((nW2 + 255) / 256), 256>>>(W2, nW2);

    g1_gemm<<<dim3(NN1 / 128, B_DIM / 128), 256, SMEM1>>>(b1, hnew);
    g2_gemm<<<dim3(NN2 / 64,  B_DIM / 128), 256, SMEM2>>>(b2, out);
}